// round 2
// baseline (speedup 1.0000x reference)
#include <cuda_runtime.h>
#include <cuda_bf16.h>

#define NN 100000
#define NE 3200000
#define CH 128

// Scratch (static device globals: allocation-free per harness rules)
__device__ int   g_is64;                  // 1 if edge_index is int64, 0 if int32
__device__ float g_deg[NN];
__device__ float g_dinv[NN];
__device__ float g_xs[(size_t)NN * CH];   // dinv[row] * (X @ W), 51.2 MB (L2-resident)

// ---------------------------------------------------------------------------
// Dtype probe: int64 indices have all-zero high words; int32 pairs do not.
// ---------------------------------------------------------------------------
__global__ void k_detect(const int2* __restrict__ ei) {
    if (threadIdx.x == 0 && blockIdx.x == 0) {
        int any_hi = 0;
#pragma unroll 8
        for (int i = 0; i < 256; i++) any_hi |= ei[i].y;
        g_is64 = (any_hi == 0) ? 1 : 0;
    }
}

__device__ __forceinline__ int edge_at(const void* __restrict__ ei, long long pos) {
    if (g_is64) return (int)((const long long*)ei)[pos];
    return ((const int*)ei)[pos];
}

// ---------------------------------------------------------------------------
// Degree: deg[i] = 1 (self loop) + #in-edges(i); dinv = rsqrt(deg)
// ---------------------------------------------------------------------------
__global__ void k_init_deg() {
    int i = blockIdx.x * blockDim.x + threadIdx.x;
    if (i < NN) g_deg[i] = 1.0f;
}

__global__ void k_deg(const void* __restrict__ ei) {
    int e = blockIdx.x * blockDim.x + threadIdx.x;
    if (e < NE) {
        int c = edge_at(ei, (long long)NE + e);   // target node
        atomicAdd(&g_deg[c], 1.0f);
    }
}

__global__ void k_rsqrt() {
    int i = blockIdx.x * blockDim.x + threadIdx.x;
    if (i < NN) g_dinv[i] = rsqrtf(g_deg[i]);
}

// ---------------------------------------------------------------------------
// GEMM: g_xs[i][c] = g_dinv[i] * sum_k X[i][k] * W[k][c]
// Block: 64 rows x 128 cols, 256 threads, each thread 8x4 register tile.
// ---------------------------------------------------------------------------
__global__ void __launch_bounds__(256) k_gemm(const float* __restrict__ X,
                                              const float* __restrict__ W) {
    __shared__ float As[16 * 68];   // [k][row], stride 68 (conflict-free, f4-aligned)
    __shared__ float Ws[16 * 128];  // [k][col]

    const int tid = threadIdx.x;
    const int bm  = blockIdx.x * 64;
    const int tx  = tid & 31;       // col group
    const int ty  = tid >> 5;       // row group
    const int r0  = ty * 8;
    const int c0  = tx * 4;

    float acc[8][4];
#pragma unroll
    for (int j = 0; j < 8; j++)
#pragma unroll
        for (int q = 0; q < 4; q++) acc[j][q] = 0.0f;

    const int arow = tid >> 2;      // 0..63
    const int aq   = tid & 3;       // 0..3 (which float4 along k)

    for (int kk = 0; kk < CH; kk += 16) {
        // Load A tile (64x16), transposed into As[k][row]
        {
            int grow = bm + arow;
            float4 av = make_float4(0.f, 0.f, 0.f, 0.f);
            if (grow < NN)
                av = *(const float4*)&X[(size_t)grow * CH + kk + aq * 4];
            As[(aq * 4 + 0) * 68 + arow] = av.x;
            As[(aq * 4 + 1) * 68 + arow] = av.y;
            As[(aq * 4 + 2) * 68 + arow] = av.z;
            As[(aq * 4 + 3) * 68 + arow] = av.w;
        }
        // Load W tile (16x128): 2 float4 per thread
#pragma unroll
        for (int t = 0; t < 2; t++) {
            int idx = tid + t * 256;            // 0..511
            int wk  = idx >> 5;
            int wc  = (idx & 31) * 4;
            *(float4*)&Ws[wk * 128 + wc] =
                *(const float4*)&W[(size_t)(kk + wk) * CH + wc];
        }
        __syncthreads();

#pragma unroll
        for (int k = 0; k < 16; k++) {
            float4 b  = *(float4*)&Ws[k * 128 + c0];
            float4 a0 = *(float4*)&As[k * 68 + r0];
            float4 a1 = *(float4*)&As[k * 68 + r0 + 4];
            float ar[8] = {a0.x, a0.y, a0.z, a0.w, a1.x, a1.y, a1.z, a1.w};
#pragma unroll
            for (int j = 0; j < 8; j++) {
                acc[j][0] += ar[j] * b.x;
                acc[j][1] += ar[j] * b.y;
                acc[j][2] += ar[j] * b.z;
                acc[j][3] += ar[j] * b.w;
            }
        }
        __syncthreads();
    }

    // Epilogue: scale by dinv[row], store to g_xs
#pragma unroll
    for (int j = 0; j < 8; j++) {
        int grow = bm + r0 + j;
        if (grow < NN) {
            float s = g_dinv[grow];
            float4 v = make_float4(s * acc[j][0], s * acc[j][1],
                                   s * acc[j][2], s * acc[j][3]);
            *(float4*)&g_xs[(size_t)grow * CH + c0] = v;
        }
    }
}

// ---------------------------------------------------------------------------
// Init out with self-loop contribution + bias:
//   out[i][c] = dinv[i] * xs[i][c] + bias[c]   (xs already carries dinv[i])
// ---------------------------------------------------------------------------
__global__ void k_init_out(float* __restrict__ out, const float* __restrict__ bias) {
    int t = blockIdx.x * blockDim.x + threadIdx.x;   // over NN*32 float4s
    if (t < NN * 32) {
        int node = t >> 5;
        int c4   = (t & 31) * 4;
        float s  = g_dinv[node];
        float4 v = *(const float4*)&g_xs[(size_t)node * CH + c4];
        float4 b = *(const float4*)&bias[c4];
        float4 o = make_float4(s * v.x + b.x, s * v.y + b.y,
                               s * v.z + b.z, s * v.w + b.w);
        *(float4*)&out[(size_t)node * CH + c4] = o;
    }
}

// ---------------------------------------------------------------------------
// Edge scatter: one warp per edge. out[col] += dinv[col] * xs[row]
// ---------------------------------------------------------------------------
__global__ void __launch_bounds__(256) k_edge(const void* __restrict__ ei,
                                              float* __restrict__ out) {
    long long gid = (long long)blockIdx.x * blockDim.x + threadIdx.x;
    int e    = (int)(gid >> 5);
    int lane = threadIdx.x & 31;
    if (e < NE) {
        int r = edge_at(ei, e);                       // source
        int c = edge_at(ei, (long long)NE + e);       // target
        float s = __ldg(&g_dinv[c]);
        float4 v = *(const float4*)&g_xs[(size_t)r * CH + lane * 4];
        float* dst = &out[(size_t)c * CH + lane * 4];
        atomicAdd(dst + 0, s * v.x);
        atomicAdd(dst + 1, s * v.y);
        atomicAdd(dst + 2, s * v.z);
        atomicAdd(dst + 3, s * v.w);
    }
}

// ---------------------------------------------------------------------------
extern "C" void kernel_launch(void* const* d_in, const int* in_sizes, int n_in,
                              void* d_out, int out_size) {
    const float* X    = (const float*)d_in[0];
    const void*  ei   = d_in[1];                 // [2, NE], int32 OR int64
    // d_in[2] = batch (unused by GCNConv)
    const float* W    = (const float*)d_in[3];
    const float* bias = (const float*)d_in[4];
    float*       out  = (float*)d_out;

    // 0) probe index dtype (device-side, deterministic, capturable)
    k_detect<<<1, 32>>>((const int2*)ei);

    // 1) degree + normalization
    k_init_deg<<<(NN + 255) / 256, 256>>>();
    k_deg<<<(NE + 255) / 256, 256>>>(ei);
    k_rsqrt<<<(NN + 255) / 256, 256>>>();

    // 2) xs = dinv[row] * (X @ W)
    k_gemm<<<(NN + 63) / 64, 256>>>(X, W);

    // 3) out = dinv*xs + bias  (self loop)
    k_init_out<<<(NN * 32 + 255) / 256, 256>>>(out, bias);

    // 4) edge scatter: warp per edge
    long long total = (long long)NE * 32;
    k_edge<<<(unsigned)((total + 255) / 256), 256>>>(ei, out);
}

// round 3
// speedup vs baseline: 2.4802x; 2.4802x over previous
#include <cuda_runtime.h>
#include <cuda_bf16.h>

#define NN 100000
#define NE 3200000
#define CH 128

// Scratch (static device globals: allocation-free per harness rules)
__device__ int   g_is64;                  // 1 if edge_index is int64, 0 if int32
__device__ int   g_cnt[NN];               // in-degree (excl. self loop)
__device__ int   g_off[NN];               // CSR offsets (exclusive scan of cnt)
__device__ int   g_cur[NN];               // scatter cursors
__device__ int   g_csr[NE];               // source ids grouped by target
__device__ float g_dinv[NN];
__device__ float g_xs[(size_t)NN * CH];   // dinv[row] * (X @ W), 51.2 MB (L2-resident)

// ---------------------------------------------------------------------------
// Dtype probe: int64 indices have all-zero high words; int32 pairs do not.
// ---------------------------------------------------------------------------
__global__ void k_detect(const int2* __restrict__ ei) {
    if (threadIdx.x == 0 && blockIdx.x == 0) {
        int any_hi = 0;
#pragma unroll 8
        for (int i = 0; i < 256; i++) any_hi |= ei[i].y;
        g_is64 = (any_hi == 0) ? 1 : 0;
    }
}

__device__ __forceinline__ int edge_at(const void* __restrict__ ei, long long pos) {
    if (g_is64) return (int)((const long long*)ei)[pos];
    return ((const int*)ei)[pos];
}

// ---------------------------------------------------------------------------
// CSR build: count -> dinv -> scan -> scatter
// ---------------------------------------------------------------------------
__global__ void k_zero_cnt() {
    int i = blockIdx.x * blockDim.x + threadIdx.x;
    if (i < NN) g_cnt[i] = 0;
}

__global__ void k_count(const void* __restrict__ ei) {
    int e = blockIdx.x * blockDim.x + threadIdx.x;
    if (e < NE) atomicAdd(&g_cnt[edge_at(ei, (long long)NE + e)], 1);
}

__global__ void k_dinv() {
    int i = blockIdx.x * blockDim.x + threadIdx.x;
    if (i < NN) g_dinv[i] = rsqrtf(1.0f + (float)g_cnt[i]);
}

// Single-block exclusive scan of g_cnt -> g_off (and g_cur copy).
__global__ void __launch_bounds__(1024) k_scan() {
    __shared__ int warp_sums[32];
    const int t    = threadIdx.x;
    const int per  = (NN + 1023) / 1024;              // 98
    const int lane = t & 31, wid = t >> 5;
    int start = t * per;
    int end   = start + per; if (end > NN) end = NN;
    if (start > NN) start = NN;

    int s = 0;
    for (int i = start; i < end; i++) s += g_cnt[i];

    // inclusive warp scan of per-thread sums
    int v = s;
#pragma unroll
    for (int o = 1; o < 32; o <<= 1) {
        int u = __shfl_up_sync(0xFFFFFFFFu, v, o);
        if (lane >= o) v += u;
    }
    if (lane == 31) warp_sums[wid] = v;
    __syncthreads();
    if (wid == 0) {
        int w = warp_sums[lane];
#pragma unroll
        for (int o = 1; o < 32; o <<= 1) {
            int u = __shfl_up_sync(0xFFFFFFFFu, w, o);
            if (lane >= o) w += u;
        }
        warp_sums[lane] = w;
    }
    __syncthreads();

    int excl = v - s + (wid > 0 ? warp_sums[wid - 1] : 0);
    int run = excl;
    for (int i = start; i < end; i++) {
        g_off[i] = run;
        g_cur[i] = run;
        run += g_cnt[i];
    }
}

__global__ void k_scatter(const void* __restrict__ ei) {
    int e = blockIdx.x * blockDim.x + threadIdx.x;
    if (e < NE) {
        int r = edge_at(ei, e);                     // source
        int c = edge_at(ei, (long long)NE + e);     // target
        int pos = atomicAdd(&g_cur[c], 1);
        g_csr[pos] = r;
    }
}

// ---------------------------------------------------------------------------
// GEMM: g_xs[i][c] = g_dinv[i] * sum_k X[i][k] * W[k][c]
// Block: 64 rows x 128 cols, 256 threads, each thread 8x4 register tile.
// ---------------------------------------------------------------------------
__global__ void __launch_bounds__(256) k_gemm(const float* __restrict__ X,
                                              const float* __restrict__ W) {
    __shared__ float As[16 * 68];   // [k][row], stride 68 (conflict-free, f4-aligned)
    __shared__ float Ws[16 * 128];  // [k][col]

    const int tid = threadIdx.x;
    const int bm  = blockIdx.x * 64;
    const int tx  = tid & 31;
    const int ty  = tid >> 5;
    const int r0  = ty * 8;
    const int c0  = tx * 4;

    float acc[8][4];
#pragma unroll
    for (int j = 0; j < 8; j++)
#pragma unroll
        for (int q = 0; q < 4; q++) acc[j][q] = 0.0f;

    const int arow = tid >> 2;
    const int aq   = tid & 3;

    for (int kk = 0; kk < CH; kk += 16) {
        {
            int grow = bm + arow;
            float4 av = make_float4(0.f, 0.f, 0.f, 0.f);
            if (grow < NN)
                av = *(const float4*)&X[(size_t)grow * CH + kk + aq * 4];
            As[(aq * 4 + 0) * 68 + arow] = av.x;
            As[(aq * 4 + 1) * 68 + arow] = av.y;
            As[(aq * 4 + 2) * 68 + arow] = av.z;
            As[(aq * 4 + 3) * 68 + arow] = av.w;
        }
#pragma unroll
        for (int t = 0; t < 2; t++) {
            int idx = tid + t * 256;
            int wk  = idx >> 5;
            int wc  = (idx & 31) * 4;
            *(float4*)&Ws[wk * 128 + wc] =
                *(const float4*)&W[(size_t)(kk + wk) * CH + wc];
        }
        __syncthreads();

#pragma unroll
        for (int k = 0; k < 16; k++) {
            float4 b  = *(float4*)&Ws[k * 128 + c0];
            float4 a0 = *(float4*)&As[k * 68 + r0];
            float4 a1 = *(float4*)&As[k * 68 + r0 + 4];
            float ar[8] = {a0.x, a0.y, a0.z, a0.w, a1.x, a1.y, a1.z, a1.w};
#pragma unroll
            for (int j = 0; j < 8; j++) {
                acc[j][0] += ar[j] * b.x;
                acc[j][1] += ar[j] * b.y;
                acc[j][2] += ar[j] * b.z;
                acc[j][3] += ar[j] * b.w;
            }
        }
        __syncthreads();
    }

#pragma unroll
    for (int j = 0; j < 8; j++) {
        int grow = bm + r0 + j;
        if (grow < NN) {
            float s = g_dinv[grow];
            float4 v = make_float4(s * acc[j][0], s * acc[j][1],
                                   s * acc[j][2], s * acc[j][3]);
            *(float4*)&g_xs[(size_t)grow * CH + c0] = v;
        }
    }
}

// ---------------------------------------------------------------------------
// Pull-mode aggregation: one warp per target node, zero atomics.
//   out[c] = dinv[c] * (xs[c] + sum_{r in N(c)} xs[r]) + bias
// ---------------------------------------------------------------------------
__global__ void __launch_bounds__(256) k_aggr(float* __restrict__ out,
                                              const float* __restrict__ bias) {
    int warp = (blockIdx.x * 256 + threadIdx.x) >> 5;
    int lane = threadIdx.x & 31;
    if (warp >= NN) return;
    const int c   = warp;
    const int off = g_off[c];
    const int n   = g_cnt[c];

    // self-loop term (xs already carries one dinv factor)
    float4 acc = *(const float4*)&g_xs[(size_t)c * CH + lane * 4];

    for (int i = 0; i < n; i += 32) {
        int chunk = n - i; if (chunk > 32) chunk = 32;
        int r = (lane < chunk) ? __ldg(&g_csr[off + i + lane]) : 0;
        for (int j = 0; j < chunk; j++) {
            int rj = __shfl_sync(0xFFFFFFFFu, r, j);
            float4 v = *(const float4*)&g_xs[(size_t)rj * CH + lane * 4];
            acc.x += v.x; acc.y += v.y; acc.z += v.z; acc.w += v.w;
        }
    }

    const float s = g_dinv[c];
    float4 b = *(const float4*)&bias[lane * 4];
    float4 o = make_float4(s * acc.x + b.x, s * acc.y + b.y,
                           s * acc.z + b.z, s * acc.w + b.w);
    *(float4*)&out[(size_t)c * CH + lane * 4] = o;
}

// ---------------------------------------------------------------------------
extern "C" void kernel_launch(void* const* d_in, const int* in_sizes, int n_in,
                              void* d_out, int out_size) {
    const float* X    = (const float*)d_in[0];
    const void*  ei   = d_in[1];                 // [2, NE], int32 OR int64
    // d_in[2] = batch (unused by GCNConv)
    const float* W    = (const float*)d_in[3];
    const float* bias = (const float*)d_in[4];
    float*       out  = (float*)d_out;

    k_detect<<<1, 32>>>((const int2*)ei);

    // CSR build
    k_zero_cnt<<<(NN + 255) / 256, 256>>>();
    k_count<<<(NE + 255) / 256, 256>>>(ei);
    k_dinv<<<(NN + 255) / 256, 256>>>();
    k_scan<<<1, 1024>>>();
    k_scatter<<<(NE + 255) / 256, 256>>>(ei);

    // xs = dinv[row] * (X @ W)
    k_gemm<<<(NN + 63) / 64, 256>>>(X, W);

    // pull-mode aggregate (warp per node)
    k_aggr<<<(NN * 32 + 255) / 256, 256>>>(out, bias);
}